// round 1
// baseline (speedup 1.0000x reference)
#include <cuda_runtime.h>
#include <cmath>

#define B_  4
#define T_  2048
#define D_  1024
#define H_  16
#define DH_ 64

// Scratch (allocation-free rule: __device__ globals)
__device__ float g_q[B_ * H_ * T_ * DH_];      // [B,H,T,dh]
__device__ float g_k[B_ * H_ * T_ * DH_];
__device__ float g_v[B_ * H_ * T_ * DH_];
__device__ float g_attn[B_ * T_ * D_];         // [B,T,D]

// ---------------------------------------------------------------------------
// GEMM 1: qkv = x @ Wqkv + bqkv, scattered into q/k/v with [B,H,T,dh] layout.
// 128x128 tile, BK=8, 256 threads, 8x8 accum per thread (split 4+4 rows/cols).
// ---------------------------------------------------------------------------
__global__ __launch_bounds__(256) void gemm_qkv_kernel(
    const float* __restrict__ A,      // [8192, 1024]
    const float* __restrict__ W,      // [1024, 3072]
    const float* __restrict__ bias)   // [3072]
{
    const int N = 3 * D_;
    const int K = D_;
    __shared__ float As[8][128];   // [k][m]
    __shared__ float Bs[8][128];   // [k][n]

    const int tid  = threadIdx.x;
    const int tx   = tid & 15;
    const int ty   = tid >> 4;
    const int tx4  = tx << 2;
    const int ty4  = ty << 2;
    const int row0 = blockIdx.y * 128;
    const int col0 = blockIdx.x * 128;

    const int a_row = tid >> 1;
    const int a_col = (tid & 1) << 2;
    const int b_row = tid >> 5;
    const int b_col = (tid & 31) << 2;

    const float* Aptr = A + (size_t)(row0 + a_row) * K + a_col;
    const float* Bptr = W + (size_t)b_row * N + col0 + b_col;

    float4 aReg = *(const float4*)Aptr;
    float4 bReg = *(const float4*)Bptr;

    float acc[8][8];
#pragma unroll
    for (int i = 0; i < 8; i++)
#pragma unroll
        for (int j = 0; j < 8; j++) acc[i][j] = 0.0f;

    for (int kt = 0; kt < K; kt += 8) {
        As[a_col + 0][a_row] = aReg.x;
        As[a_col + 1][a_row] = aReg.y;
        As[a_col + 2][a_row] = aReg.z;
        As[a_col + 3][a_row] = aReg.w;
        *(float4*)&Bs[b_row][b_col] = bReg;
        __syncthreads();

        if (kt + 8 < K) {
            aReg = *(const float4*)(Aptr + kt + 8);
            bReg = *(const float4*)(Bptr + (size_t)(kt + 8) * N);
        }

#pragma unroll
        for (int k = 0; k < 8; k++) {
            float a[8], b[8];
            *(float4*)&a[0] = *(const float4*)&As[k][ty4];
            *(float4*)&a[4] = *(const float4*)&As[k][64 + ty4];
            *(float4*)&b[0] = *(const float4*)&Bs[k][tx4];
            *(float4*)&b[4] = *(const float4*)&Bs[k][64 + tx4];
#pragma unroll
            for (int i = 0; i < 8; i++)
#pragma unroll
                for (int j = 0; j < 8; j++)
                    acc[i][j] += a[i] * b[j];
        }
        __syncthreads();
    }

    // Epilogue: section (q/k/v) is constant per block since 1024 % 128 == 0.
    const int sec = col0 >> 10;
    float* dst = (sec == 0) ? g_q : (sec == 1) ? g_k : g_v;

#pragma unroll
    for (int ih = 0; ih < 2; ih++) {
#pragma unroll
        for (int ii = 0; ii < 4; ii++) {
            const int r  = row0 + ih * 64 + ty4 + ii;
            const int bb = r >> 11;       // batch
            const int t  = r & 2047;      // time
#pragma unroll
            for (int jh = 0; jh < 2; jh++) {
                const int c    = col0 + jh * 64 + tx4;
                const int cc   = c & 1023;
                const int head = cc >> 6;
                const int d    = cc & 63;
                float4 v;
                v.x = acc[ih * 4 + ii][jh * 4 + 0] + bias[c + 0];
                v.y = acc[ih * 4 + ii][jh * 4 + 1] + bias[c + 1];
                v.z = acc[ih * 4 + ii][jh * 4 + 2] + bias[c + 2];
                v.w = acc[ih * 4 + ii][jh * 4 + 3] + bias[c + 3];
                *(float4*)&dst[((size_t)(bb * H_ + head) * T_ + t) * DH_ + d] = v;
            }
        }
    }
}

// ---------------------------------------------------------------------------
// RoPE on q and k in place. inv_freq table passed by value (computed on host
// in double precision -> matches jax fp32 rope cache to ~ulp).
// ---------------------------------------------------------------------------
struct RopeInv { float v[32]; };

__global__ __launch_bounds__(256) void rope_kernel(RopeInv tab) {
    const int idx = blockIdx.x * blockDim.x + threadIdx.x;   // 4,194,304 total
    const int d   = idx & 31;
    const int row = idx >> 5;          // bh*T + t, row < 131072
    const int t   = row & (T_ - 1);

    const float ang = (float)t * tab.v[d];
    float s, c;
    sincosf(ang, &s, &c);              // accurate version (large args OK)

    const size_t base = (size_t)row * DH_;
    {
        float x1 = g_q[base + d], x2 = g_q[base + d + 32];
        g_q[base + d]      = x1 * c - x2 * s;
        g_q[base + d + 32] = x1 * s + x2 * c;
    }
    {
        float x1 = g_k[base + d], x2 = g_k[base + d + 32];
        g_k[base + d]      = x1 * c - x2 * s;
        g_k[base + d + 32] = x1 * s + x2 * c;
    }
}

// ---------------------------------------------------------------------------
// Flash attention, fp32. CTA = 64 queries of one (b,h); loops 32 KV tiles of
// 64 keys. K held d-major (transposed) in smem for conflict-free LDS.128.
// Thread map: 16x16 grid, each thread 4 rows x 4 cols.
// ---------------------------------------------------------------------------
#define ATTN_SMEM_FLOATS (64 * 64 + 64 * 68 + 64 * 64 + 64 * 64)
#define ATTN_SMEM_BYTES  (ATTN_SMEM_FLOATS * 4)

__global__ __launch_bounds__(256) void attn_kernel() {
    extern __shared__ float sm[];
    float* Qs  = sm;                    // [64][64], pre-scaled by 1/8
    float* Kts = Qs + 64 * 64;          // [64][68]  (d-major, padded stride)
    float* Vs  = Kts + 64 * 68;         // [64][64]
    float* Ps  = Vs + 64 * 64;          // [64][64]

    const int tid = threadIdx.x;
    const int tx  = tid & 15;
    const int ty  = tid >> 4;
    const int tx4 = tx << 2;
    const int ty4 = ty << 2;

    const int bh = blockIdx.y;          // b*16 + h
    const int qb = blockIdx.x;          // query tile

    const float* Qg  = g_q + (size_t)bh * (T_ * DH_) + (size_t)qb * (64 * DH_);
    const float* Kg0 = g_k + (size_t)bh * (T_ * DH_);
    const float* Vg0 = g_v + (size_t)bh * (T_ * DH_);

    for (int i = tid; i < 1024; i += 256) {
        float4 v = ((const float4*)Qg)[i];
        v.x *= 0.125f; v.y *= 0.125f; v.z *= 0.125f; v.w *= 0.125f;
        ((float4*)Qs)[i] = v;
    }

    float4 acc[4];
    float m_i[4], l_i[4];
#pragma unroll
    for (int ii = 0; ii < 4; ii++) {
        acc[ii] = make_float4(0.f, 0.f, 0.f, 0.f);
        m_i[ii] = -1e30f;
        l_i[ii] = 0.f;
    }

    for (int kt = 0; kt < 32; kt++) {
        __syncthreads();   // protect Vs/Ps/Kts from previous iteration readers
        const float4* Kg = (const float4*)(Kg0 + (size_t)kt * 4096);
        const float4* Vg = (const float4*)(Vg0 + (size_t)kt * 4096);
        for (int i = tid; i < 1024; i += 256) {
            const int r  = i >> 4;          // key row j
            const int c4 = (i & 15) << 2;   // d
            float4 kv = Kg[i];
            Kts[(c4 + 0) * 68 + r] = kv.x;
            Kts[(c4 + 1) * 68 + r] = kv.y;
            Kts[(c4 + 2) * 68 + r] = kv.z;
            Kts[(c4 + 3) * 68 + r] = kv.w;
            ((float4*)Vs)[i] = Vg[i];
        }
        __syncthreads();

        // S = Qs @ K^T  (rows i = ty4+ii, cols j = tx4+jj)
        float4 s4[4];
#pragma unroll
        for (int ii = 0; ii < 4; ii++) s4[ii] = make_float4(0.f, 0.f, 0.f, 0.f);

#pragma unroll
        for (int d = 0; d < 64; d += 4) {
            const float4 k0 = *(const float4*)(Kts + (d + 0) * 68 + tx4);
            const float4 k1 = *(const float4*)(Kts + (d + 1) * 68 + tx4);
            const float4 k2 = *(const float4*)(Kts + (d + 2) * 68 + tx4);
            const float4 k3 = *(const float4*)(Kts + (d + 3) * 68 + tx4);
#pragma unroll
            for (int ii = 0; ii < 4; ii++) {
                const float4 q = *(const float4*)(Qs + (ty4 + ii) * 64 + d);
                s4[ii].x += q.x * k0.x + q.y * k1.x + q.z * k2.x + q.w * k3.x;
                s4[ii].y += q.x * k0.y + q.y * k1.y + q.z * k2.y + q.w * k3.y;
                s4[ii].z += q.x * k0.z + q.y * k1.z + q.z * k2.z + q.w * k3.z;
                s4[ii].w += q.x * k0.w + q.y * k1.w + q.z * k2.w + q.w * k3.w;
            }
        }

        // Online softmax update per row (reduce across the 16 tx lanes).
#pragma unroll
        for (int ii = 0; ii < 4; ii++) {
            float m = fmaxf(fmaxf(s4[ii].x, s4[ii].y), fmaxf(s4[ii].z, s4[ii].w));
            m = fmaxf(m, __shfl_xor_sync(0xffffffffu, m, 8));
            m = fmaxf(m, __shfl_xor_sync(0xffffffffu, m, 4));
            m = fmaxf(m, __shfl_xor_sync(0xffffffffu, m, 2));
            m = fmaxf(m, __shfl_xor_sync(0xffffffffu, m, 1));
            const float mnew = fmaxf(m_i[ii], m);
            const float corr = __expf(m_i[ii] - mnew);
            m_i[ii] = mnew;
            float4 p;
            p.x = __expf(s4[ii].x - mnew);
            p.y = __expf(s4[ii].y - mnew);
            p.z = __expf(s4[ii].z - mnew);
            p.w = __expf(s4[ii].w - mnew);
            float rs = p.x + p.y + p.z + p.w;
            rs += __shfl_xor_sync(0xffffffffu, rs, 8);
            rs += __shfl_xor_sync(0xffffffffu, rs, 4);
            rs += __shfl_xor_sync(0xffffffffu, rs, 2);
            rs += __shfl_xor_sync(0xffffffffu, rs, 1);
            l_i[ii] = l_i[ii] * corr + rs;
            acc[ii].x *= corr; acc[ii].y *= corr; acc[ii].z *= corr; acc[ii].w *= corr;
            *(float4*)(Ps + (ty4 + ii) * 64 + tx4) = p;
        }
        __syncthreads();

        // O += P @ V  (rows i = ty4+ii, cols d = tx4+dd)
#pragma unroll
        for (int j = 0; j < 64; j += 4) {
            const float4 v0 = *(const float4*)(Vs + (j + 0) * 64 + tx4);
            const float4 v1 = *(const float4*)(Vs + (j + 1) * 64 + tx4);
            const float4 v2 = *(const float4*)(Vs + (j + 2) * 64 + tx4);
            const float4 v3 = *(const float4*)(Vs + (j + 3) * 64 + tx4);
#pragma unroll
            for (int ii = 0; ii < 4; ii++) {
                const float4 p = *(const float4*)(Ps + (ty4 + ii) * 64 + j);
                acc[ii].x += p.x * v0.x + p.y * v1.x + p.z * v2.x + p.w * v3.x;
                acc[ii].y += p.x * v0.y + p.y * v1.y + p.z * v2.y + p.w * v3.y;
                acc[ii].z += p.x * v0.z + p.y * v1.z + p.z * v2.z + p.w * v3.z;
                acc[ii].w += p.x * v0.w + p.y * v1.w + p.z * v2.w + p.w * v3.w;
            }
        }
    }

    // Normalize and write [B,T,D]
    const int bb = bh >> 4;
    const int h  = bh & 15;
#pragma unroll
    for (int ii = 0; ii < 4; ii++) {
        const float inv = 1.0f / l_i[ii];
        const int t = qb * 64 + ty4 + ii;
        float4 o;
        o.x = acc[ii].x * inv;
        o.y = acc[ii].y * inv;
        o.z = acc[ii].z * inv;
        o.w = acc[ii].w * inv;
        *(float4*)(g_attn + ((size_t)(bb * T_ + t)) * D_ + h * DH_ + tx4) = o;
    }
}

// ---------------------------------------------------------------------------
// GEMM 2: out = attn @ Wproj + bproj
// ---------------------------------------------------------------------------
__global__ __launch_bounds__(256) void gemm_proj_kernel(
    const float* __restrict__ W,      // [1024, 1024]
    const float* __restrict__ bias,   // [1024]
    float* __restrict__ C)            // [8192, 1024]
{
    const int N = D_;
    const int K = D_;
    __shared__ float As[8][128];
    __shared__ float Bs[8][128];

    const int tid  = threadIdx.x;
    const int tx   = tid & 15;
    const int ty   = tid >> 4;
    const int tx4  = tx << 2;
    const int ty4  = ty << 2;
    const int row0 = blockIdx.y * 128;
    const int col0 = blockIdx.x * 128;

    const int a_row = tid >> 1;
    const int a_col = (tid & 1) << 2;
    const int b_row = tid >> 5;
    const int b_col = (tid & 31) << 2;

    const float* Aptr = g_attn + (size_t)(row0 + a_row) * K + a_col;
    const float* Bptr = W + (size_t)b_row * N + col0 + b_col;

    float4 aReg = *(const float4*)Aptr;
    float4 bReg = *(const float4*)Bptr;

    float acc[8][8];
#pragma unroll
    for (int i = 0; i < 8; i++)
#pragma unroll
        for (int j = 0; j < 8; j++) acc[i][j] = 0.0f;

    for (int kt = 0; kt < K; kt += 8) {
        As[a_col + 0][a_row] = aReg.x;
        As[a_col + 1][a_row] = aReg.y;
        As[a_col + 2][a_row] = aReg.z;
        As[a_col + 3][a_row] = aReg.w;
        *(float4*)&Bs[b_row][b_col] = bReg;
        __syncthreads();

        if (kt + 8 < K) {
            aReg = *(const float4*)(Aptr + kt + 8);
            bReg = *(const float4*)(Bptr + (size_t)(kt + 8) * N);
        }

#pragma unroll
        for (int k = 0; k < 8; k++) {
            float a[8], b[8];
            *(float4*)&a[0] = *(const float4*)&As[k][ty4];
            *(float4*)&a[4] = *(const float4*)&As[k][64 + ty4];
            *(float4*)&b[0] = *(const float4*)&Bs[k][tx4];
            *(float4*)&b[4] = *(const float4*)&Bs[k][64 + tx4];
#pragma unroll
            for (int i = 0; i < 8; i++)
#pragma unroll
                for (int j = 0; j < 8; j++)
                    acc[i][j] += a[i] * b[j];
        }
        __syncthreads();
    }

#pragma unroll
    for (int ih = 0; ih < 2; ih++) {
#pragma unroll
        for (int ii = 0; ii < 4; ii++) {
            const int r = row0 + ih * 64 + ty4 + ii;
#pragma unroll
            for (int jh = 0; jh < 2; jh++) {
                const int c = col0 + jh * 64 + tx4;
                float4 v;
                v.x = acc[ih * 4 + ii][jh * 4 + 0] + bias[c + 0];
                v.y = acc[ih * 4 + ii][jh * 4 + 1] + bias[c + 1];
                v.z = acc[ih * 4 + ii][jh * 4 + 2] + bias[c + 2];
                v.w = acc[ih * 4 + ii][jh * 4 + 3] + bias[c + 3];
                *(float4*)&C[(size_t)r * N + c] = v;
            }
        }
    }
}

// ---------------------------------------------------------------------------
extern "C" void kernel_launch(void* const* d_in, const int* in_sizes, int n_in,
                              void* d_out, int out_size)
{
    const float* x     = (const float*)d_in[0];
    const float* Wqkv  = (const float*)d_in[1];
    const float* bqkv  = (const float*)d_in[2];
    const float* Wproj = (const float*)d_in[3];
    const float* bproj = (const float*)d_in[4];
    float* out = (float*)d_out;

    // 1) QKV GEMM with head-layout scatter
    gemm_qkv_kernel<<<dim3(24, 64), 256>>>(x, Wqkv, bqkv);

    // 2) RoPE (inv_freq computed host-side in double, passed by value)
    RopeInv tab;
    for (int d = 0; d < 32; d++)
        tab.v[d] = (float)(1.0 / pow(10000.0, (double)((float)d / 32.0f)));
    rope_kernel<<<16384, 256>>>(tab);

    // 3) Flash attention (dynamic smem > 48KB)
    cudaFuncSetAttribute((const void*)attn_kernel,
                         cudaFuncAttributeMaxDynamicSharedMemorySize,
                         ATTN_SMEM_BYTES);
    attn_kernel<<<dim3(32, 64), 256, ATTN_SMEM_BYTES>>>();

    // 4) Output projection
    gemm_proj_kernel<<<dim3(8, 64), 256>>>(Wproj, bproj, out);
}

// round 11
// speedup vs baseline: 1.0835x; 1.0835x over previous
#include <cuda_runtime.h>
#include <cuda_bf16.h>
#include <cmath>
#include <cstdint>

#define B_  4
#define T_  2048
#define D_  1024
#define H_  16
#define DH_ 64

// ---------------------------------------------------------------------------
// Scratch — IDENTICAL static set to the passing R1 kernel (128 MiB total).
// ---------------------------------------------------------------------------
__device__ __align__(16) float g_q[B_ * H_ * T_ * DH_];      // [B,H,T,dh] fp32
__device__ __align__(16) float g_k[B_ * H_ * T_ * DH_];
__device__ __align__(16) float g_v[B_ * H_ * T_ * DH_];
__device__ __align__(16) float g_attn[B_ * T_ * D_];         // [B,T,D] fp32

// ---------------------------------------------------------------------------
// PTX helpers: ldmatrix / mma.sync only
// ---------------------------------------------------------------------------
struct U4  { uint32_t x, y, z, w; };
struct F4a { float    x, y, z, w; };

__device__ __forceinline__ uint32_t smem_u32(const void* p) {
    uint32_t a;
    asm("{ .reg .u64 t; cvta.to.shared.u64 t, %1; cvt.u32.u64 %0, t; }" : "=r"(a) : "l"(p));
    return a;
}
__device__ __forceinline__ void ldsm4(U4& r, uint32_t addr) {
    asm volatile("ldmatrix.sync.aligned.m8n8.x4.shared.b16 {%0,%1,%2,%3}, [%4];"
                 : "=r"(r.x), "=r"(r.y), "=r"(r.z), "=r"(r.w) : "r"(addr));
}
__device__ __forceinline__ void ldsm4t(U4& r, uint32_t addr) {
    asm volatile("ldmatrix.sync.aligned.m8n8.x4.trans.shared.b16 {%0,%1,%2,%3}, [%4];"
                 : "=r"(r.x), "=r"(r.y), "=r"(r.z), "=r"(r.w) : "r"(addr));
}
__device__ __forceinline__ void mma(F4a& d, const U4& a, uint32_t b0, uint32_t b1) {
    asm volatile(
        "mma.sync.aligned.m16n8k16.row.col.f32.bf16.bf16.f32 "
        "{%0,%1,%2,%3}, {%4,%5,%6,%7}, {%8,%9}, {%0,%1,%2,%3};"
        : "+f"(d.x), "+f"(d.y), "+f"(d.z), "+f"(d.w)
        : "r"(a.x), "r"(a.y), "r"(a.z), "r"(a.w), "r"(b0), "r"(b1));
}

// Convert 8 fp32 (two float4) -> 16B hi chunk + 16B lo chunk (bf16x2 packed)
__device__ __forceinline__ void cvt8(const float4 f0, const float4 f1,
                                     uint4& hi, uint4& lo)
{
    __nv_bfloat16 h0 = __float2bfloat16_rn(f0.x);
    __nv_bfloat16 h1 = __float2bfloat16_rn(f0.y);
    __nv_bfloat16 h2 = __float2bfloat16_rn(f0.z);
    __nv_bfloat16 h3 = __float2bfloat16_rn(f0.w);
    __nv_bfloat16 h4 = __float2bfloat16_rn(f1.x);
    __nv_bfloat16 h5 = __float2bfloat16_rn(f1.y);
    __nv_bfloat16 h6 = __float2bfloat16_rn(f1.z);
    __nv_bfloat16 h7 = __float2bfloat16_rn(f1.w);
    __nv_bfloat16 l0 = __float2bfloat16_rn(f0.x - __bfloat162float(h0));
    __nv_bfloat16 l1 = __float2bfloat16_rn(f0.y - __bfloat162float(h1));
    __nv_bfloat16 l2 = __float2bfloat16_rn(f0.z - __bfloat162float(h2));
    __nv_bfloat16 l3 = __float2bfloat16_rn(f0.w - __bfloat162float(h3));
    __nv_bfloat16 l4 = __float2bfloat16_rn(f1.x - __bfloat162float(h4));
    __nv_bfloat16 l5 = __float2bfloat16_rn(f1.y - __bfloat162float(h5));
    __nv_bfloat16 l6 = __float2bfloat16_rn(f1.z - __bfloat162float(h6));
    __nv_bfloat16 l7 = __float2bfloat16_rn(f1.w - __bfloat162float(h7));
    __nv_bfloat162 p;
    p = __nv_bfloat162(h0, h1); hi.x = *(uint32_t*)&p;
    p = __nv_bfloat162(h2, h3); hi.y = *(uint32_t*)&p;
    p = __nv_bfloat162(h4, h5); hi.z = *(uint32_t*)&p;
    p = __nv_bfloat162(h6, h7); hi.w = *(uint32_t*)&p;
    p = __nv_bfloat162(l0, l1); lo.x = *(uint32_t*)&p;
    p = __nv_bfloat162(l2, l3); lo.y = *(uint32_t*)&p;
    p = __nv_bfloat162(l4, l5); lo.z = *(uint32_t*)&p;
    p = __nv_bfloat162(l6, l7); lo.w = *(uint32_t*)&p;
}

// ---------------------------------------------------------------------------
// Low-register fused convert+mma GEMM:  C[M,N] = A[M,K] @ W[K,N] + bias
//   CTA tile 64(M) x 64(N), BK=64, static 32KB smem, 8 warps (2m x 4n),
//   warp tile 32x16, acc = 16 regs/thread. Phased: A-fill, B-fill, mma.
//   3 passes AhBh + AhBl + AlBh (fp32 accum).
//   MODE 1: A = x, W = Wqkv[1024,3072], scatter into g_q/k/v.
//   MODE 0: A = g_attn, W = Wproj[1024,1024], write out.
// ---------------------------------------------------------------------------
#define GK   1024
#define BK   64
#define NKB  (GK / BK)   // 16

#define MMA3(Dst, b0h, b1h, b0l, b1l)  \
    mma(Dst, aH, b0h, b1h);            \
    mma(Dst, aH, b0l, b1l);            \
    mma(Dst, aL, b0h, b1h);

#define EPI(C, MT, NT) do {                                                        \
    const int r_lo = row0 + wm * 32 + (MT) * 16 + (lane >> 2);                     \
    const int r_hi = r_lo + 8;                                                     \
    const int col  = col0 + wn * 16 + (NT) * 8 + 2 * (lane & 3);                   \
    const float b0 = bias[col], b1 = bias[col + 1];                                \
    float2 vlo = make_float2((C).x + b0, (C).y + b1);                              \
    float2 vhi = make_float2((C).z + b0, (C).w + b1);                              \
    if (MODE == 0) {                                                               \
        *(float2*)(out + (size_t)r_lo * 1024 + col) = vlo;                         \
        *(float2*)(out + (size_t)r_hi * 1024 + col) = vhi;                         \
    } else {                                                                       \
        const int sec  = col >> 10;                                               \
        const int cc   = col & 1023;                                              \
        const int head = cc >> 6;                                                 \
        const int dd   = cc & 63;                                                 \
        float* buf = (sec == 0) ? g_q : (sec == 1) ? g_k : g_v;                    \
        { const int bb = r_lo >> 11, t = r_lo & 2047;                              \
          *(float2*)(buf + ((size_t)(bb * H_ + head) * T_ + t) * DH_ + dd) = vlo; }\
        { const int bb = r_hi >> 11, t = r_hi & 2047;                              \
          *(float2*)(buf + ((size_t)(bb * H_ + head) * T_ + t) * DH_ + dd) = vhi; }\
    }                                                                              \
} while (0)

template <int MODE>
__global__ __launch_bounds__(256) void gemm_fused_kernel(
    const float* __restrict__ Ain,   // MODE 1: x [8192,1024]; MODE 0: ignored
    const float* __restrict__ W,     // [1024, Ntot] row-major
    const float* __restrict__ bias, float* __restrict__ out)
{
    const int Ntot = (MODE == 1) ? 3072 : 1024;

    // 32 KB static shared: Ah[64][128B] Al Bh[64k][128B n] Bl
    __shared__ __align__(16) char smem[32768];
    const uint32_t sb = smem_u32(smem);
    const int O_AH = 0, O_AL = 8192, O_BH = 16384, O_BL = 24576;

    const int tid  = threadIdx.x;
    const int lane = tid & 31;
    const int wid  = tid >> 5;
    const int wm   = wid & 1;       // 2 warps along M (32 rows each)
    const int wn   = wid >> 1;      // 4 warps along N (16 cols each)

    const int col0 = blockIdx.x * 64;
    const int row0 = blockIdx.y * 64;

    const float* A = (MODE == 0) ? (const float*)g_attn : Ain;

    // Copy-phase coordinates: 64 rows x 64 fp32; 4 threads/row, 16 fp32/thread.
    const int cpR = tid >> 2;            // row 0..63
    const int cpC = (tid & 3) * 16;      // starting fp32 column
    const int cpU = (tid & 3) * 2;       // starting 16B unit (of 8 per 128B row)

    F4a c00 = {0,0,0,0}, c01 = {0,0,0,0};   // mt0, nt0/1
    F4a c10 = {0,0,0,0}, c11 = {0,0,0,0};   // mt1, nt0/1

    const int a_r  = wm * 32 + (lane & 15); // + mt*16 (16%8==0 -> same &7)
    const int a_s7 = a_r & 7;
    const int b_rl = lane & 15;             // + ks*16
    const int b_ch = wn * 2 + (lane >> 4);  // 16B n-chunk within 128B row

#pragma unroll 1
    for (int kb = 0; kb < NKB; kb++) {
        const int kbase = kb * BK;

        __syncthreads();   // previous iteration's mma reads complete

        // ---- A phase: load 16 fp32, convert, store swizzled hi/lo ----
        {
            const float* src = A + (size_t)(row0 + cpR) * GK + kbase + cpC;
            float4 f0 = *(const float4*)(src + 0);
            float4 f1 = *(const float4*)(src + 4);
            float4 f2 = *(const float4*)(src + 8);
            float4 f3 = *(const float4*)(src + 12);
            uint4 hi, lo;
            cvt8(f0, f1, hi, lo);
            uint32_t off = cpR * 128 + (((cpU + 0) ^ (cpR & 7)) << 4);
            *(uint4*)(smem + O_AH + off) = hi;
            *(uint4*)(smem + O_AL + off) = lo;
            cvt8(f2, f3, hi, lo);
            off = cpR * 128 + (((cpU + 1) ^ (cpR & 7)) << 4);
            *(uint4*)(smem + O_AH + off) = hi;
            *(uint4*)(smem + O_AL + off) = lo;
        }
        // ---- B phase: [k][n] tile, row = k ----
        {
            const float* src = W + (size_t)(kbase + cpR) * Ntot + col0 + cpC;
            float4 f0 = *(const float4*)(src + 0);
            float4 f1 = *(const float4*)(src + 4);
            float4 f2 = *(const float4*)(src + 8);
            float4 f3 = *(const float4*)(src + 12);
            uint4 hi, lo;
            cvt8(f0, f1, hi, lo);
            uint32_t off = cpR * 128 + (((cpU + 0) ^ (cpR & 7)) << 4);
            *(uint4*)(smem + O_BH + off) = hi;
            *(uint4*)(smem + O_BL + off) = lo;
            cvt8(f2, f3, hi, lo);
            off = cpR * 128 + (((cpU + 1) ^ (cpR & 7)) << 4);
            *(uint4*)(smem + O_BH + off) = hi;
            *(uint4*)(smem + O_BL + off) = lo;
        }

        __syncthreads();   // tiles complete

        // ---- mma: 4 k-steps of 16 ----
#pragma unroll 1
        for (int ks = 0; ks < 4; ks++) {
            const int br = ks * 16 + b_rl;
            const uint32_t boff = br * 128 + ((b_ch ^ (br & 7)) << 4);
            U4 bH, bL;
            ldsm4t(bH, sb + O_BH + boff);
            ldsm4t(bL, sb + O_BL + boff);

            const uint32_t asw = (uint32_t)(((2 * ks + (lane >> 4)) ^ a_s7) << 4);
            U4 aH, aL;
            // mt = 0
            ldsm4(aH, sb + O_AH + a_r * 128 + asw);
            ldsm4(aL, sb + O_AL + a_r * 128 + asw);
            MMA3(c00, bH.x, bH.y, bL.x, bL.y)
            MMA3(c01, bH.z, bH.w, bL.z, bL.w)
            // mt = 1
            ldsm4(aH, sb + O_AH + (a_r + 16) * 128 + asw);
            ldsm4(aL, sb + O_AL + (a_r + 16) * 128 + asw);
            MMA3(c10, bH.x, bH.y, bL.x, bL.y)
            MMA3(c11, bH.z, bH.w, bL.z, bL.w)
        }
    }

    EPI(c00, 0, 0); EPI(c01, 0, 1);
    EPI(c10, 1, 0); EPI(c11, 1, 1);
}

// ---------------------------------------------------------------------------
// RoPE on q and k in place (fp32) — verbatim from passing R1.
// ---------------------------------------------------------------------------
struct RopeInv { float v[32]; };

__global__ __launch_bounds__(256) void rope_kernel(RopeInv tab) {
    const int idx = blockIdx.x * blockDim.x + threadIdx.x;
    const int d   = idx & 31;
    const int row = idx >> 5;
    const int t   = row & (T_ - 1);

    const float ang = (float)t * tab.v[d];
    float s, c;
    sincosf(ang, &s, &c);

    const size_t base = (size_t)row * DH_;
    {
        float x1 = g_q[base + d], x2 = g_q[base + d + 32];
        g_q[base + d]      = x1 * c - x2 * s;
        g_q[base + d + 32] = x1 * s + x2 * c;
    }
    {
        float x1 = g_k[base + d], x2 = g_k[base + d + 32];
        g_k[base + d]      = x1 * c - x2 * s;
        g_k[base + d + 32] = x1 * s + x2 * c;
    }
}

// ---------------------------------------------------------------------------
// Flash attention, fp32 SIMT — verbatim from passing R1.
// ---------------------------------------------------------------------------
#define ATTN_SMEM_FLOATS (64 * 64 + 64 * 68 + 64 * 64 + 64 * 64)
#define ATTN_SMEM_BYTES  (ATTN_SMEM_FLOATS * 4)

__global__ __launch_bounds__(256) void attn_kernel() {
    extern __shared__ float sm[];
    float* Qs  = sm;
    float* Kts = Qs + 64 * 64;
    float* Vs  = Kts + 64 * 68;
    float* Ps  = Vs + 64 * 64;

    const int tid = threadIdx.x;
    const int tx  = tid & 15;
    const int ty  = tid >> 4;
    const int tx4 = tx << 2;
    const int ty4 = ty << 2;

    const int bh = blockIdx.y;
    const int qb = blockIdx.x;

    const float* Qg  = g_q + (size_t)bh * (T_ * DH_) + (size_t)qb * (64 * DH_);
    const float* Kg0 = g_k + (size_t)bh * (T_ * DH_);
    const float* Vg0 = g_v + (size_t)bh * (T_ * DH_);

    for (int i = tid; i < 1024; i += 256) {
        float4 v = ((const float4*)Qg)[i];
        v.x *= 0.125f; v.y *= 0.125f; v.z *= 0.125f; v.w *= 0.125f;
        ((float4*)Qs)[i] = v;
    }

    float4 acc[4];
    float m_i[4], l_i[4];
#pragma unroll
    for (int ii = 0; ii < 4; ii++) {
        acc[ii] = make_float4(0.f, 0.f, 0.f, 0.f);
        m_i[ii] = -1e30f;
        l_i[ii] = 0.f;
    }

    for (int kt = 0; kt < 32; kt++) {
        __syncthreads();
        const float4* Kg = (const float4*)(Kg0 + (size_t)kt * 4096);
        const float4* Vg = (const float4*)(Vg0 + (size_t)kt * 4096);
        for (int i = tid; i < 1024; i += 256) {
            const int r  = i >> 4;
            const int c4 = (i & 15) << 2;
            float4 kv = Kg[i];
            Kts[(c4 + 0) * 68 + r] = kv.x;
            Kts[(c4 + 1) * 68 + r] = kv.y;
            Kts[(c4 + 2) * 68 + r] = kv.z;
            Kts[(c4 + 3) * 68 + r] = kv.w;
            ((float4*)Vs)[i] = Vg[i];
        }
        __syncthreads();

        float4 s4[4];
#pragma unroll
        for (int ii = 0; ii < 4; ii++) s4[ii] = make_float4(0.f, 0.f, 0.f, 0.f);

#pragma unroll
        for (int d = 0; d < 64; d += 4) {
            const float4 k0 = *(const float4*)(Kts + (d + 0) * 68 + tx4);
            const float4 k1 = *(const float4*)(Kts + (d + 1) * 68 + tx4);
            const float4 k2 = *(const float4*)(Kts + (d + 2) * 68 + tx4);
            const float4 k3 = *(const float4*)(Kts + (d + 3) * 68 + tx4);
#pragma unroll
            for (int ii = 0; ii < 4; ii++) {
                const float4 q = *(const float4*)(Qs + (ty4 + ii) * 64 + d);
                s4[ii].x += q.x * k0.x + q.y * k1.x + q.z * k2.x + q.w * k3.x;
                s4[ii].y += q.x * k0.y + q.y * k1.y + q.z * k2.y + q.w * k3.y;
                s4[ii].z += q.x * k0.z + q.y * k1.z + q.z * k2.z + q.w * k3.z;
                s4[ii].w += q.x * k0.w + q.y * k1.w + q.z * k2.w + q.w * k3.w;
            }
        }

#pragma unroll
        for (int ii = 0; ii < 4; ii++) {
            float m = fmaxf(fmaxf(s4[ii].x, s4[ii].y), fmaxf(s4[ii].z, s4[ii].w));
            m = fmaxf(m, __shfl_xor_sync(0xffffffffu, m, 8));
            m = fmaxf(m, __shfl_xor_sync(0xffffffffu, m, 4));
            m = fmaxf(m, __shfl_xor_sync(0xffffffffu, m, 2));
            m = fmaxf(m, __shfl_xor_sync(0xffffffffu, m, 1));
            const float mnew = fmaxf(m_i[ii], m);
            const float corr = __expf(m_i[ii] - mnew);
            m_i[ii] = mnew;
            float4 p;
            p.x = __expf(s4[ii].x - mnew);
            p.y = __expf(s4[ii].y - mnew);
            p.z = __expf(s4[ii].z - mnew);
            p.w = __expf(s4[ii].w - mnew);
            float rs = p.x + p.y + p.z + p.w;
            rs += __shfl_xor_sync(0xffffffffu, rs, 8);
            rs += __shfl_xor_sync(0xffffffffu, rs, 4);
            rs += __shfl_xor_sync(0xffffffffu, rs, 2);
            rs += __shfl_xor_sync(0xffffffffu, rs, 1);
            l_i[ii] = l_i[ii] * corr + rs;
            acc[ii].x *= corr; acc[ii].y *= corr; acc[ii].z *= corr; acc[ii].w *= corr;
            *(float4*)(Ps + (ty4 + ii) * 64 + tx4) = p;
        }
        __syncthreads();

#pragma unroll
        for (int j = 0; j < 64; j += 4) {
            const float4 v0 = *(const float4*)(Vs + (j + 0) * 64 + tx4);
            const float4 v1 = *(const float4*)(Vs + (j + 1) * 64 + tx4);
            const float4 v2 = *(const float4*)(Vs + (j + 2) * 64 + tx4);
            const float4 v3 = *(const float4*)(Vs + (j + 3) * 64 + tx4);
#pragma unroll
            for (int ii = 0; ii < 4; ii++) {
                const float4 p = *(const float4*)(Ps + (ty4 + ii) * 64 + j);
                acc[ii].x += p.x * v0.x + p.y * v1.x + p.z * v2.x + p.w * v3.x;
                acc[ii].y += p.x * v0.y + p.y * v1.y + p.z * v2.y + p.w * v3.y;
                acc[ii].z += p.x * v0.z + p.y * v1.z + p.z * v2.z + p.w * v3.z;
                acc[ii].w += p.x * v0.w + p.y * v1.w + p.z * v2.w + p.w * v3.w;
            }
        }
    }

    const int bb = bh >> 4;
    const int h  = bh & 15;
#pragma unroll
    for (int ii = 0; ii < 4; ii++) {
        const float inv = 1.0f / l_i[ii];
        const int t = qb * 64 + ty4 + ii;
        float4 o;
        o.x = acc[ii].x * inv;
        o.y = acc[ii].y * inv;
        o.z = acc[ii].z * inv;
        o.w = acc[ii].w * inv;
        *(float4*)(g_attn + ((size_t)(bb * T_ + t)) * D_ + h * DH_ + tx4) = o;
    }
}

// ---------------------------------------------------------------------------
extern "C" void kernel_launch(void* const* d_in, const int* in_sizes, int n_in,
                              void* d_out, int out_size)
{
    const float* x     = (const float*)d_in[0];
    const float* Wqkv  = (const float*)d_in[1];
    const float* bqkv  = (const float*)d_in[2];
    const float* Wproj = (const float*)d_in[3];
    const float* bproj = (const float*)d_in[4];
    float* out = (float*)d_out;

    cudaFuncSetAttribute((const void*)attn_kernel,
                         cudaFuncAttributeMaxDynamicSharedMemorySize, ATTN_SMEM_BYTES);

    // 1) QKV GEMM (fused fp32->bf16-split mma.sync, 64x64 tiles) + head scatter
    gemm_fused_kernel<1><<<dim3(48, 128), 256>>>(x, Wqkv, bqkv, nullptr);

    // 2) RoPE
    RopeInv tab;
    for (int d = 0; d < 32; d++)
        tab.v[d] = (float)(1.0 / pow(10000.0, (double)((float)d / 32.0f)));
    rope_kernel<<<16384, 256>>>(tab);

    // 3) Flash attention (fp32 SIMT)
    attn_kernel<<<dim3(32, 64), 256, ATTN_SMEM_BYTES>>>();

    // 4) Output projection
    gemm_fused_kernel<0><<<dim3(16, 128), 256>>>(nullptr, Wproj, bproj, out);
}

// round 12
// speedup vs baseline: 1.6105x; 1.4863x over previous
#include <cuda_runtime.h>
#include <cuda_bf16.h>
#include <cmath>
#include <cstdint>

#define B_  4
#define T_  2048
#define D_  1024
#define H_  16
#define DH_ 64

// ---------------------------------------------------------------------------
// Scratch — identical static set to the passing R11 kernel.
// ---------------------------------------------------------------------------
__device__ __align__(16) float g_q[B_ * H_ * T_ * DH_];      // [B,H,T,dh] fp32
__device__ __align__(16) float g_k[B_ * H_ * T_ * DH_];
__device__ __align__(16) float g_v[B_ * H_ * T_ * DH_];
__device__ __align__(16) float g_attn[B_ * T_ * D_];         // [B,T,D] fp32

// ---------------------------------------------------------------------------
// PTX helpers: ldmatrix / mma.sync only
// ---------------------------------------------------------------------------
struct U4  { uint32_t x, y, z, w; };
struct F4a { float    x, y, z, w; };

__device__ __forceinline__ uint32_t smem_u32(const void* p) {
    uint32_t a;
    asm("{ .reg .u64 t; cvta.to.shared.u64 t, %1; cvt.u32.u64 %0, t; }" : "=r"(a) : "l"(p));
    return a;
}
__device__ __forceinline__ void ldsm4(U4& r, uint32_t addr) {
    asm volatile("ldmatrix.sync.aligned.m8n8.x4.shared.b16 {%0,%1,%2,%3}, [%4];"
                 : "=r"(r.x), "=r"(r.y), "=r"(r.z), "=r"(r.w) : "r"(addr));
}
__device__ __forceinline__ void ldsm4t(U4& r, uint32_t addr) {
    asm volatile("ldmatrix.sync.aligned.m8n8.x4.trans.shared.b16 {%0,%1,%2,%3}, [%4];"
                 : "=r"(r.x), "=r"(r.y), "=r"(r.z), "=r"(r.w) : "r"(addr));
}
__device__ __forceinline__ void mma(F4a& d, const U4& a, uint32_t b0, uint32_t b1) {
    asm volatile(
        "mma.sync.aligned.m16n8k16.row.col.f32.bf16.bf16.f32 "
        "{%0,%1,%2,%3}, {%4,%5,%6,%7}, {%8,%9}, {%0,%1,%2,%3};"
        : "+f"(d.x), "+f"(d.y), "+f"(d.z), "+f"(d.w)
        : "r"(a.x), "r"(a.y), "r"(a.z), "r"(a.w), "r"(b0), "r"(b1));
}

// Convert 8 fp32 (two float4) -> 16B hi chunk + 16B lo chunk (bf16x2 packed)
__device__ __forceinline__ void cvt8(const float4 f0, const float4 f1,
                                     uint4& hi, uint4& lo)
{
    __nv_bfloat16 h0 = __float2bfloat16_rn(f0.x);
    __nv_bfloat16 h1 = __float2bfloat16_rn(f0.y);
    __nv_bfloat16 h2 = __float2bfloat16_rn(f0.z);
    __nv_bfloat16 h3 = __float2bfloat16_rn(f0.w);
    __nv_bfloat16 h4 = __float2bfloat16_rn(f1.x);
    __nv_bfloat16 h5 = __float2bfloat16_rn(f1.y);
    __nv_bfloat16 h6 = __float2bfloat16_rn(f1.z);
    __nv_bfloat16 h7 = __float2bfloat16_rn(f1.w);
    __nv_bfloat16 l0 = __float2bfloat16_rn(f0.x - __bfloat162float(h0));
    __nv_bfloat16 l1 = __float2bfloat16_rn(f0.y - __bfloat162float(h1));
    __nv_bfloat16 l2 = __float2bfloat16_rn(f0.z - __bfloat162float(h2));
    __nv_bfloat16 l3 = __float2bfloat16_rn(f0.w - __bfloat162float(h3));
    __nv_bfloat16 l4 = __float2bfloat16_rn(f1.x - __bfloat162float(h4));
    __nv_bfloat16 l5 = __float2bfloat16_rn(f1.y - __bfloat162float(h5));
    __nv_bfloat16 l6 = __float2bfloat16_rn(f1.z - __bfloat162float(h6));
    __nv_bfloat16 l7 = __float2bfloat16_rn(f1.w - __bfloat162float(h7));
    __nv_bfloat162 p;
    p = __nv_bfloat162(h0, h1); hi.x = *(uint32_t*)&p;
    p = __nv_bfloat162(h2, h3); hi.y = *(uint32_t*)&p;
    p = __nv_bfloat162(h4, h5); hi.z = *(uint32_t*)&p;
    p = __nv_bfloat162(h6, h7); hi.w = *(uint32_t*)&p;
    p = __nv_bfloat162(l0, l1); lo.x = *(uint32_t*)&p;
    p = __nv_bfloat162(l2, l3); lo.y = *(uint32_t*)&p;
    p = __nv_bfloat162(l4, l5); lo.z = *(uint32_t*)&p;
    p = __nv_bfloat162(l6, l7); lo.w = *(uint32_t*)&p;
}

#define MMA3(Dst, b0h, b1h, b0l, b1l)  \
    mma(Dst, aH, b0h, b1h);            \
    mma(Dst, aH, b0l, b1l);            \
    mma(Dst, aL, b0h, b1h);

// ---------------------------------------------------------------------------
// Low-register fused convert+mma GEMM (UNCHANGED from passing R11).
// ---------------------------------------------------------------------------
#define GK   1024
#define BK   64
#define NKB  (GK / BK)   // 16

#define EPI(C, MT, NT) do {                                                        \
    const int r_lo = row0 + wm * 32 + (MT) * 16 + (lane >> 2);                     \
    const int r_hi = r_lo + 8;                                                     \
    const int col  = col0 + wn * 16 + (NT) * 8 + 2 * (lane & 3);                   \
    const float b0 = bias[col], b1 = bias[col + 1];                                \
    float2 vlo = make_float2((C).x + b0, (C).y + b1);                              \
    float2 vhi = make_float2((C).z + b0, (C).w + b1);                              \
    if (MODE == 0) {                                                               \
        *(float2*)(out + (size_t)r_lo * 1024 + col) = vlo;                         \
        *(float2*)(out + (size_t)r_hi * 1024 + col) = vhi;                         \
    } else {                                                                       \
        const int sec  = col >> 10;                                               \
        const int cc   = col & 1023;                                              \
        const int head = cc >> 6;                                                 \
        const int dd   = cc & 63;                                                 \
        float* buf = (sec == 0) ? g_q : (sec == 1) ? g_k : g_v;                    \
        { const int bb = r_lo >> 11, t = r_lo & 2047;                              \
          *(float2*)(buf + ((size_t)(bb * H_ + head) * T_ + t) * DH_ + dd) = vlo; }\
        { const int bb = r_hi >> 11, t = r_hi & 2047;                              \
          *(float2*)(buf + ((size_t)(bb * H_ + head) * T_ + t) * DH_ + dd) = vhi; }\
    }                                                                              \
} while (0)

template <int MODE>
__global__ __launch_bounds__(256) void gemm_fused_kernel(
    const float* __restrict__ Ain,
    const float* __restrict__ W,
    const float* __restrict__ bias, float* __restrict__ out)
{
    const int Ntot = (MODE == 1) ? 3072 : 1024;

    __shared__ __align__(16) char smem[32768];
    const uint32_t sb = smem_u32(smem);
    const int O_AH = 0, O_AL = 8192, O_BH = 16384, O_BL = 24576;

    const int tid  = threadIdx.x;
    const int lane = tid & 31;
    const int wid  = tid >> 5;
    const int wm   = wid & 1;
    const int wn   = wid >> 1;

    const int col0 = blockIdx.x * 64;
    const int row0 = blockIdx.y * 64;

    const float* A = (MODE == 0) ? (const float*)g_attn : Ain;

    const int cpR = tid >> 2;
    const int cpC = (tid & 3) * 16;
    const int cpU = (tid & 3) * 2;

    F4a c00 = {0,0,0,0}, c01 = {0,0,0,0};
    F4a c10 = {0,0,0,0}, c11 = {0,0,0,0};

    const int a_r  = wm * 32 + (lane & 15);
    const int a_s7 = a_r & 7;
    const int b_rl = lane & 15;
    const int b_ch = wn * 2 + (lane >> 4);

#pragma unroll 1
    for (int kb = 0; kb < NKB; kb++) {
        const int kbase = kb * BK;

        __syncthreads();

        {
            const float* src = A + (size_t)(row0 + cpR) * GK + kbase + cpC;
            float4 f0 = *(const float4*)(src + 0);
            float4 f1 = *(const float4*)(src + 4);
            float4 f2 = *(const float4*)(src + 8);
            float4 f3 = *(const float4*)(src + 12);
            uint4 hi, lo;
            cvt8(f0, f1, hi, lo);
            uint32_t off = cpR * 128 + (((cpU + 0) ^ (cpR & 7)) << 4);
            *(uint4*)(smem + O_AH + off) = hi;
            *(uint4*)(smem + O_AL + off) = lo;
            cvt8(f2, f3, hi, lo);
            off = cpR * 128 + (((cpU + 1) ^ (cpR & 7)) << 4);
            *(uint4*)(smem + O_AH + off) = hi;
            *(uint4*)(smem + O_AL + off) = lo;
        }
        {
            const float* src = W + (size_t)(kbase + cpR) * Ntot + col0 + cpC;
            float4 f0 = *(const float4*)(src + 0);
            float4 f1 = *(const float4*)(src + 4);
            float4 f2 = *(const float4*)(src + 8);
            float4 f3 = *(const float4*)(src + 12);
            uint4 hi, lo;
            cvt8(f0, f1, hi, lo);
            uint32_t off = cpR * 128 + (((cpU + 0) ^ (cpR & 7)) << 4);
            *(uint4*)(smem + O_BH + off) = hi;
            *(uint4*)(smem + O_BL + off) = lo;
            cvt8(f2, f3, hi, lo);
            off = cpR * 128 + (((cpU + 1) ^ (cpR & 7)) << 4);
            *(uint4*)(smem + O_BH + off) = hi;
            *(uint4*)(smem + O_BL + off) = lo;
        }

        __syncthreads();

#pragma unroll 1
        for (int ks = 0; ks < 4; ks++) {
            const int br = ks * 16 + b_rl;
            const uint32_t boff = br * 128 + ((b_ch ^ (br & 7)) << 4);
            U4 bH, bL;
            ldsm4t(bH, sb + O_BH + boff);
            ldsm4t(bL, sb + O_BL + boff);

            const uint32_t asw = (uint32_t)(((2 * ks + (lane >> 4)) ^ a_s7) << 4);
            U4 aH, aL;
            ldsm4(aH, sb + O_AH + a_r * 128 + asw);
            ldsm4(aL, sb + O_AL + a_r * 128 + asw);
            MMA3(c00, bH.x, bH.y, bL.x, bL.y)
            MMA3(c01, bH.z, bH.w, bL.z, bL.w)
            ldsm4(aH, sb + O_AH + (a_r + 16) * 128 + asw);
            ldsm4(aL, sb + O_AL + (a_r + 16) * 128 + asw);
            MMA3(c10, bH.x, bH.y, bL.x, bL.y)
            MMA3(c11, bH.z, bH.w, bL.z, bL.w)
        }
    }

    EPI(c00, 0, 0); EPI(c01, 0, 1);
    EPI(c10, 1, 0); EPI(c11, 1, 1);
}

// ---------------------------------------------------------------------------
// RoPE on q and k in place (fp32) — verbatim from passing R1.
// ---------------------------------------------------------------------------
struct RopeInv { float v[32]; };

__global__ __launch_bounds__(256) void rope_kernel(RopeInv tab) {
    const int idx = blockIdx.x * blockDim.x + threadIdx.x;
    const int d   = idx & 31;
    const int row = idx >> 5;
    const int t   = row & (T_ - 1);

    const float ang = (float)t * tab.v[d];
    float s, c;
    sincosf(ang, &s, &c);

    const size_t base = (size_t)row * DH_;
    {
        float x1 = g_q[base + d], x2 = g_q[base + d + 32];
        g_q[base + d]      = x1 * c - x2 * s;
        g_q[base + d + 32] = x1 * s + x2 * c;
    }
    {
        float x1 = g_k[base + d], x2 = g_k[base + d + 32];
        g_k[base + d]      = x1 * c - x2 * s;
        g_k[base + d + 32] = x1 * s + x2 * c;
    }
}

// ---------------------------------------------------------------------------
// Tensor-core flash attention (mma.sync, bf16 hi/lo split on both matmuls).
//   CTA = 64 queries of one (b,h); loop 32 KV tiles of 64 keys.
//   Warps 2(M)x4(N): S warp-tile 32x16, O warp-tile 32x16 (d-cols).
//   smem layout (bytes):
//     Qh 0      Ql 8192   Kh 16384  Kl 24576  Vh 32768  Vl 40960
//     Ph 49152  Pl 57344  Ps 65536 (64 x 68 fp32 = 17408)
//     ms 82944  ls 83200  cs 83456   -> total 83712
// ---------------------------------------------------------------------------
#define A_QH 0
#define A_QL 8192
#define A_KH 16384
#define A_KL 24576
#define A_VH 32768
#define A_VL 40960
#define A_PH 49152
#define A_PL 57344
#define A_PS 65536
#define A_MS 82944
#define A_LS 83200
#define A_CS 83456
#define ATTN_SMEM 83712

__global__ __launch_bounds__(256) void attn_mma_kernel() {
    extern __shared__ char sm8[];
    const uint32_t sb = smem_u32(sm8);
    float* Ps = (float*)(sm8 + A_PS);     // [64][68]
    float* ms = (float*)(sm8 + A_MS);
    float* ls = (float*)(sm8 + A_LS);
    float* cs = (float*)(sm8 + A_CS);

    const int tid  = threadIdx.x;
    const int lane = tid & 31;
    const int wid  = tid >> 5;
    const int wm   = wid & 1;       // M: 32 rows each
    const int wn   = wid >> 1;      // N: 16 cols each

    const int bh = blockIdx.y;
    const int qb = blockIdx.x;

    const float* Qg = g_q + (size_t)bh * (T_ * DH_) + (size_t)qb * (64 * DH_);
    const float* Kg = g_k + (size_t)bh * (T_ * DH_);
    const float* Vg = g_v + (size_t)bh * (T_ * DH_);

    const int cpR = tid >> 2;            // row 0..63
    const int cpC = (tid & 3) * 16;      // fp32 col
    const int cpU = (tid & 3) * 2;       // 16B unit

    // ---- load Q (pre-scaled by 1/8), convert to hi/lo ----
    {
        const float* src = Qg + (size_t)cpR * DH_ + cpC;
        float4 f0 = *(const float4*)(src + 0);
        float4 f1 = *(const float4*)(src + 4);
        float4 f2 = *(const float4*)(src + 8);
        float4 f3 = *(const float4*)(src + 12);
        f0.x *= 0.125f; f0.y *= 0.125f; f0.z *= 0.125f; f0.w *= 0.125f;
        f1.x *= 0.125f; f1.y *= 0.125f; f1.z *= 0.125f; f1.w *= 0.125f;
        f2.x *= 0.125f; f2.y *= 0.125f; f2.z *= 0.125f; f2.w *= 0.125f;
        f3.x *= 0.125f; f3.y *= 0.125f; f3.z *= 0.125f; f3.w *= 0.125f;
        uint4 hi, lo;
        cvt8(f0, f1, hi, lo);
        uint32_t off = cpR * 128 + (((cpU + 0) ^ (cpR & 7)) << 4);
        *(uint4*)(sm8 + A_QH + off) = hi;
        *(uint4*)(sm8 + A_QL + off) = lo;
        cvt8(f2, f3, hi, lo);
        off = cpR * 128 + (((cpU + 1) ^ (cpR & 7)) << 4);
        *(uint4*)(sm8 + A_QH + off) = hi;
        *(uint4*)(sm8 + A_QL + off) = lo;
    }
    if (tid < 64) { ms[tid] = -1e30f; ls[tid] = 0.0f; }

    F4a o00 = {0,0,0,0}, o01 = {0,0,0,0};
    F4a o10 = {0,0,0,0}, o11 = {0,0,0,0};

    const int a_r  = wm * 32 + (lane & 15);   // + mt*16
    const int a_s7 = a_r & 7;
    // K (non-trans B): row covers n (keys)
    const int k_r  = wn * 16 + ((lane >> 4) << 3) + (lane & 7);
    const int k_c  = (lane >> 3) & 1;
    // V (trans B): like GEMM B path
    const int v_rl = lane & 15;
    const int v_ch = wn * 2 + (lane >> 4);

#pragma unroll 1
    for (int kt = 0; kt < 32; kt++) {
        __syncthreads();   // protect K/V/P from previous iteration's mma reads

        // ---- copy K, V tiles (keys kt*64 + cpR) ----
        {
            const float* src = Kg + (size_t)(kt * 64 + cpR) * DH_ + cpC;
            float4 f0 = *(const float4*)(src + 0);
            float4 f1 = *(const float4*)(src + 4);
            float4 f2 = *(const float4*)(src + 8);
            float4 f3 = *(const float4*)(src + 12);
            uint4 hi, lo;
            cvt8(f0, f1, hi, lo);
            uint32_t off = cpR * 128 + (((cpU + 0) ^ (cpR & 7)) << 4);
            *(uint4*)(sm8 + A_KH + off) = hi;
            *(uint4*)(sm8 + A_KL + off) = lo;
            cvt8(f2, f3, hi, lo);
            off = cpR * 128 + (((cpU + 1) ^ (cpR & 7)) << 4);
            *(uint4*)(sm8 + A_KH + off) = hi;
            *(uint4*)(sm8 + A_KL + off) = lo;
        }
        {
            const float* src = Vg + (size_t)(kt * 64 + cpR) * DH_ + cpC;
            float4 f0 = *(const float4*)(src + 0);
            float4 f1 = *(const float4*)(src + 4);
            float4 f2 = *(const float4*)(src + 8);
            float4 f3 = *(const float4*)(src + 12);
            uint4 hi, lo;
            cvt8(f0, f1, hi, lo);
            uint32_t off = cpR * 128 + (((cpU + 0) ^ (cpR & 7)) << 4);
            *(uint4*)(sm8 + A_VH + off) = hi;
            *(uint4*)(sm8 + A_VL + off) = lo;
            cvt8(f2, f3, hi, lo);
            off = cpR * 128 + (((cpU + 1) ^ (cpR & 7)) << 4);
            *(uint4*)(sm8 + A_VH + off) = hi;
            *(uint4*)(sm8 + A_VL + off) = lo;
        }
        __syncthreads();

        // ---- S = Q @ K^T (3-pass split) ----
        {
            F4a s00 = {0,0,0,0}, s01 = {0,0,0,0};
            F4a s10 = {0,0,0,0}, s11 = {0,0,0,0};
#pragma unroll 1
            for (int ks = 0; ks < 4; ks++) {
                const uint32_t koff = k_r * 128 + (((2 * ks + k_c) ^ (k_r & 7)) << 4);
                U4 bH, bL;
                ldsm4(bH, sb + A_KH + koff);
                ldsm4(bL, sb + A_KL + koff);
                const uint32_t asw = (uint32_t)(((2 * ks + (lane >> 4)) ^ a_s7) << 4);
                U4 aH, aL;
                ldsm4(aH, sb + A_QH + a_r * 128 + asw);
                ldsm4(aL, sb + A_QL + a_r * 128 + asw);
                MMA3(s00, bH.x, bH.y, bL.x, bL.y)
                MMA3(s01, bH.z, bH.w, bL.z, bL.w)
                ldsm4(aH, sb + A_QH + (a_r + 16) * 128 + asw);
                ldsm4(aL, sb + A_QL + (a_r + 16) * 128 + asw);
                MMA3(s10, bH.x, bH.y, bL.x, bL.y)
                MMA3(s11, bH.z, bH.w, bL.z, bL.w)
            }
            // write S fragments to Ps [64][68]
            const int r0 = wm * 32 + (lane >> 2);
            const int cB = wn * 16 + 2 * (lane & 3);
            *(float2*)(Ps + (r0 +  0) * 68 + cB)     = make_float2(s00.x, s00.y);
            *(float2*)(Ps + (r0 +  8) * 68 + cB)     = make_float2(s00.z, s00.w);
            *(float2*)(Ps + (r0 +  0) * 68 + cB + 8) = make_float2(s01.x, s01.y);
            *(float2*)(Ps + (r0 +  8) * 68 + cB + 8) = make_float2(s01.z, s01.w);
            *(float2*)(Ps + (r0 + 16) * 68 + cB)     = make_float2(s10.x, s10.y);
            *(float2*)(Ps + (r0 + 24) * 68 + cB)     = make_float2(s10.z, s10.w);
            *(float2*)(Ps + (r0 + 16) * 68 + cB + 8) = make_float2(s11.x, s11.y);
            *(float2*)(Ps + (r0 + 24) * 68 + cB + 8) = make_float2(s11.z, s11.w);
        }
        __syncthreads();

        // ---- online softmax (4 threads per row) + P -> hi/lo bf16 ----
        {
            const int row = tid >> 2;
            const int q   = tid & 3;
            const float* pr = Ps + row * 68 + q * 16;
            float4 p0 = *(const float4*)(pr + 0);
            float4 p1 = *(const float4*)(pr + 4);
            float4 p2 = *(const float4*)(pr + 8);
            float4 p3 = *(const float4*)(pr + 12);
            float mx = fmaxf(fmaxf(fmaxf(p0.x, p0.y), fmaxf(p0.z, p0.w)),
                             fmaxf(fmaxf(p1.x, p1.y), fmaxf(p1.z, p1.w)));
            mx = fmaxf(mx, fmaxf(fmaxf(fmaxf(p2.x, p2.y), fmaxf(p2.z, p2.w)),
                                 fmaxf(fmaxf(p3.x, p3.y), fmaxf(p3.z, p3.w))));
            mx = fmaxf(mx, __shfl_xor_sync(0xffffffffu, mx, 1));
            mx = fmaxf(mx, __shfl_xor_sync(0xffffffffu, mx, 2));
            const float m_old = ms[row];
            const float m_new = fmaxf(m_old, mx);
            p0.x = __expf(p0.x - m_new); p0.y = __expf(p0.y - m_new);
            p0.z = __expf(p0.z - m_new); p0.w = __expf(p0.w - m_new);
            p1.x = __expf(p1.x - m_new); p1.y = __expf(p1.y - m_new);
            p1.z = __expf(p1.z - m_new); p1.w = __expf(p1.w - m_new);
            p2.x = __expf(p2.x - m_new); p2.y = __expf(p2.y - m_new);
            p2.z = __expf(p2.z - m_new); p2.w = __expf(p2.w - m_new);
            p3.x = __expf(p3.x - m_new); p3.y = __expf(p3.y - m_new);
            p3.z = __expf(p3.z - m_new); p3.w = __expf(p3.w - m_new);
            float sum = p0.x + p0.y + p0.z + p0.w + p1.x + p1.y + p1.z + p1.w
                      + p2.x + p2.y + p2.z + p2.w + p3.x + p3.y + p3.z + p3.w;
            sum += __shfl_xor_sync(0xffffffffu, sum, 1);
            sum += __shfl_xor_sync(0xffffffffu, sum, 2);
            const float corr = __expf(m_old - m_new);
            if (q == 0) {
                ms[row] = m_new;
                cs[row] = corr;
                ls[row] = ls[row] * corr + sum;
            }
            uint4 hi, lo;
            cvt8(p0, p1, hi, lo);
            uint32_t off = row * 128 + (((cpU + 0) ^ (row & 7)) << 4);
            *(uint4*)(sm8 + A_PH + off) = hi;
            *(uint4*)(sm8 + A_PL + off) = lo;
            cvt8(p2, p3, hi, lo);
            off = row * 128 + (((cpU + 1) ^ (row & 7)) << 4);
            *(uint4*)(sm8 + A_PH + off) = hi;
            *(uint4*)(sm8 + A_PL + off) = lo;
        }
        __syncthreads();

        // ---- rescale O and accumulate O += P @ V (3-pass split) ----
        {
            const int r0 = wm * 32 + (lane >> 2);
            const float c0l = cs[r0],      c0h = cs[r0 + 8];
            const float c1l = cs[r0 + 16], c1h = cs[r0 + 24];
            o00.x *= c0l; o00.y *= c0l; o00.z *= c0h; o00.w *= c0h;
            o01.x *= c0l; o01.y *= c0l; o01.z *= c0h; o01.w *= c0h;
            o10.x *= c1l; o10.y *= c1l; o10.z *= c1h; o10.w *= c1h;
            o11.x *= c1l; o11.y *= c1l; o11.z *= c1h; o11.w *= c1h;
#pragma unroll 1
            for (int ks = 0; ks < 4; ks++) {
                const int vr = ks * 16 + v_rl;
                const uint32_t voff = vr * 128 + ((v_ch ^ (vr & 7)) << 4);
                U4 bH, bL;
                ldsm4t(bH, sb + A_VH + voff);
                ldsm4t(bL, sb + A_VL + voff);
                const uint32_t asw = (uint32_t)(((2 * ks + (lane >> 4)) ^ a_s7) << 4);
                U4 aH, aL;
                ldsm4(aH, sb + A_PH + a_r * 128 + asw);
                ldsm4(aL, sb + A_PL + a_r * 128 + asw);
                MMA3(o00, bH.x, bH.y, bL.x, bL.y)
                MMA3(o01, bH.z, bH.w, bL.z, bL.w)
                ldsm4(aH, sb + A_PH + (a_r + 16) * 128 + asw);
                ldsm4(aL, sb + A_PL + (a_r + 16) * 128 + asw);
                MMA3(o10, bH.x, bH.y, bL.x, bL.y)
                MMA3(o11, bH.z, bH.w, bL.z, bL.w)
            }
        }
    }

    // ---- epilogue: normalize and write [B,T,D] ----
    {
        const int r0  = wm * 32 + (lane >> 2);
        const int dcB = wn * 16 + 2 * (lane & 3);
        const float i0l = 1.0f / ls[r0],      i0h = 1.0f / ls[r0 + 8];
        const float i1l = 1.0f / ls[r0 + 16], i1h = 1.0f / ls[r0 + 24];
        const int bb = bh >> 4;
        const int h  = bh & 15;
        float* obase = g_attn + ((size_t)(bb * T_ + qb * 64)) * D_ + h * DH_;
        // rows r0+{0,8,16,24}, cols dcB and dcB+8
        *(float2*)(obase + (size_t)(r0 +  0) * D_ + dcB)     = make_float2(o00.x * i0l, o00.y * i0l);
        *(float2*)(obase + (size_t)(r0 +  8) * D_ + dcB)     = make_float2(o00.z * i0h, o00.w * i0h);
        *(float2*)(obase + (size_t)(r0 +  0) * D_ + dcB + 8) = make_float2(o01.x * i0l, o01.y * i0l);
        *(float2*)(obase + (size_t)(r0 +  8) * D_ + dcB + 8) = make_float2(o01.z * i0h, o01.w * i0h);
        *(float2*)(obase + (size_t)(r0 + 16) * D_ + dcB)     = make_float2(o10.x * i1l, o10.y * i1l);
        *(float2*)(obase + (size_t)(r0 + 24) * D_ + dcB)     = make_float2(o10.z * i1h, o10.w * i1h);
        *(float2*)(obase + (size_t)(r0 + 16) * D_ + dcB + 8) = make_float2(o11.x * i1l, o11.y * i1l);
        *(float2*)(obase + (size_t)(r0 + 24) * D_ + dcB + 8) = make_float2(o11.z * i1h, o11.w * i1h);
    }
}

// ---------------------------------------------------------------------------
extern "C" void kernel_launch(void* const* d_in, const int* in_sizes, int n_in,
                              void* d_out, int out_size)
{
    const float* x     = (const float*)d_in[0];
    const float* Wqkv  = (const float*)d_in[1];
    const float* bqkv  = (const float*)d_in[2];
    const float* Wproj = (const float*)d_in[3];
    const float* bproj = (const float*)d_in[4];
    float* out = (float*)d_out;

    cudaFuncSetAttribute((const void*)attn_mma_kernel,
                         cudaFuncAttributeMaxDynamicSharedMemorySize, ATTN_SMEM);

    // 1) QKV GEMM (proven R11) + head scatter
    gemm_fused_kernel<1><<<dim3(48, 128), 256>>>(x, Wqkv, bqkv, nullptr);

    // 2) RoPE
    RopeInv tab;
    for (int d = 0; d < 32; d++)
        tab.v[d] = (float)(1.0 / pow(10000.0, (double)((float)d / 32.0f)));
    rope_kernel<<<16384, 256>>>(tab);

    // 3) Flash attention (mma.sync, hi/lo split)
    attn_mma_kernel<<<dim3(32, 64), 256, ATTN_SMEM>>>();

    // 4) Output projection (proven R11)
    gemm_fused_kernel<0><<<dim3(16, 128), 256>>>(nullptr, Wproj, bproj, out);
}

// round 13
// speedup vs baseline: 1.8372x; 1.1408x over previous
#include <cuda_runtime.h>
#include <cuda_bf16.h>
#include <cmath>
#include <cstdint>

#define B_  4
#define T_  2048
#define D_  1024
#define H_  16
#define DH_ 64

// ---------------------------------------------------------------------------
// Scratch — identical static set to the passing R11/R12 kernels.
// ---------------------------------------------------------------------------
__device__ __align__(16) float g_q[B_ * H_ * T_ * DH_];      // [B,H,T,dh] fp32
__device__ __align__(16) float g_k[B_ * H_ * T_ * DH_];
__device__ __align__(16) float g_v[B_ * H_ * T_ * DH_];
__device__ __align__(16) float g_attn[B_ * T_ * D_];         // [B,T,D] fp32

// ---------------------------------------------------------------------------
// PTX helpers: ldmatrix / mma.sync only
// ---------------------------------------------------------------------------
struct U4  { uint32_t x, y, z, w; };
struct F4a { float    x, y, z, w; };

__device__ __forceinline__ uint32_t smem_u32(const void* p) {
    uint32_t a;
    asm("{ .reg .u64 t; cvta.to.shared.u64 t, %1; cvt.u32.u64 %0, t; }" : "=r"(a) : "l"(p));
    return a;
}
__device__ __forceinline__ void ldsm4(U4& r, uint32_t addr) {
    asm volatile("ldmatrix.sync.aligned.m8n8.x4.shared.b16 {%0,%1,%2,%3}, [%4];"
                 : "=r"(r.x), "=r"(r.y), "=r"(r.z), "=r"(r.w) : "r"(addr));
}
__device__ __forceinline__ void ldsm4t(U4& r, uint32_t addr) {
    asm volatile("ldmatrix.sync.aligned.m8n8.x4.trans.shared.b16 {%0,%1,%2,%3}, [%4];"
                 : "=r"(r.x), "=r"(r.y), "=r"(r.z), "=r"(r.w) : "r"(addr));
}
__device__ __forceinline__ void mma(F4a& d, const U4& a, uint32_t b0, uint32_t b1) {
    asm volatile(
        "mma.sync.aligned.m16n8k16.row.col.f32.bf16.bf16.f32 "
        "{%0,%1,%2,%3}, {%4,%5,%6,%7}, {%8,%9}, {%0,%1,%2,%3};"
        : "+f"(d.x), "+f"(d.y), "+f"(d.z), "+f"(d.w)
        : "r"(a.x), "r"(a.y), "r"(a.z), "r"(a.w), "r"(b0), "r"(b1));
}

// Convert 8 fp32 (two float4) -> 16B hi chunk + 16B lo chunk (bf16x2 packed)
__device__ __forceinline__ void cvt8(const float4 f0, const float4 f1,
                                     uint4& hi, uint4& lo)
{
    __nv_bfloat16 h0 = __float2bfloat16_rn(f0.x);
    __nv_bfloat16 h1 = __float2bfloat16_rn(f0.y);
    __nv_bfloat16 h2 = __float2bfloat16_rn(f0.z);
    __nv_bfloat16 h3 = __float2bfloat16_rn(f0.w);
    __nv_bfloat16 h4 = __float2bfloat16_rn(f1.x);
    __nv_bfloat16 h5 = __float2bfloat16_rn(f1.y);
    __nv_bfloat16 h6 = __float2bfloat16_rn(f1.z);
    __nv_bfloat16 h7 = __float2bfloat16_rn(f1.w);
    __nv_bfloat16 l0 = __float2bfloat16_rn(f0.x - __bfloat162float(h0));
    __nv_bfloat16 l1 = __float2bfloat16_rn(f0.y - __bfloat162float(h1));
    __nv_bfloat16 l2 = __float2bfloat16_rn(f0.z - __bfloat162float(h2));
    __nv_bfloat16 l3 = __float2bfloat16_rn(f0.w - __bfloat162float(h3));
    __nv_bfloat16 l4 = __float2bfloat16_rn(f1.x - __bfloat162float(h4));
    __nv_bfloat16 l5 = __float2bfloat16_rn(f1.y - __bfloat162float(h5));
    __nv_bfloat16 l6 = __float2bfloat16_rn(f1.z - __bfloat162float(h6));
    __nv_bfloat16 l7 = __float2bfloat16_rn(f1.w - __bfloat162float(h7));
    __nv_bfloat162 p;
    p = __nv_bfloat162(h0, h1); hi.x = *(uint32_t*)&p;
    p = __nv_bfloat162(h2, h3); hi.y = *(uint32_t*)&p;
    p = __nv_bfloat162(h4, h5); hi.z = *(uint32_t*)&p;
    p = __nv_bfloat162(h6, h7); hi.w = *(uint32_t*)&p;
    p = __nv_bfloat162(l0, l1); lo.x = *(uint32_t*)&p;
    p = __nv_bfloat162(l2, l3); lo.y = *(uint32_t*)&p;
    p = __nv_bfloat162(l4, l5); lo.z = *(uint32_t*)&p;
    p = __nv_bfloat162(l6, l7); lo.w = *(uint32_t*)&p;
}

#define MMA3(Dst, b0h, b1h, b0l, b1l)  \
    mma(Dst, aH, b0h, b1h);            \
    mma(Dst, aH, b0l, b1l);            \
    mma(Dst, aL, b0h, b1h);

// ---------------------------------------------------------------------------
// Fused convert+mma GEMM, WIDE tile:  C[M,N] = A[M,K] @ W[K,N] + bias
//   CTA tile 64(M) x 128(N), BK=64, 48KB dynamic smem, 8 warps (2m x 4n),
//   warp tile 32x32, acc = 32 regs/thread. Phased A-fill, B-fill, mma.
//   B tile rows are 256B (two 128B swizzle halves).
// ---------------------------------------------------------------------------
#define GK   1024
#define BK   64
#define NKB  (GK / BK)   // 16
#define G_AH 0
#define G_AL 8192
#define G_BH 16384
#define G_BL 32768
#define GEMM_SMEM 49152

#define EPI(C, MT, NT) do {                                                        \
    const int r_lo = row0 + wm * 32 + (MT) * 16 + (lane >> 2);                     \
    const int r_hi = r_lo + 8;                                                     \
    const int col  = col0 + wn * 32 + (NT) * 8 + 2 * (lane & 3);                   \
    const float b0 = bias[col], b1 = bias[col + 1];                                \
    float2 vlo = make_float2((C).x + b0, (C).y + b1);                              \
    float2 vhi = make_float2((C).z + b0, (C).w + b1);                              \
    if (MODE == 0) {                                                               \
        *(float2*)(out + (size_t)r_lo * 1024 + col) = vlo;                         \
        *(float2*)(out + (size_t)r_hi * 1024 + col) = vhi;                         \
    } else {                                                                       \
        const int sec  = col >> 10;                                               \
        const int cc   = col & 1023;                                              \
        const int head = cc >> 6;                                                 \
        const int dd   = cc & 63;                                                 \
        float* buf = (sec == 0) ? g_q : (sec == 1) ? g_k : g_v;                    \
        { const int bb = r_lo >> 11, t = r_lo & 2047;                              \
          *(float2*)(buf + ((size_t)(bb * H_ + head) * T_ + t) * DH_ + dd) = vlo; }\
        { const int bb = r_hi >> 11, t = r_hi & 2047;                              \
          *(float2*)(buf + ((size_t)(bb * H_ + head) * T_ + t) * DH_ + dd) = vhi; }\
    }                                                                              \
} while (0)

template <int MODE>
__global__ __launch_bounds__(256) void gemm_fused_kernel(
    const float* __restrict__ Ain,   // MODE 1: x [8192,1024]; MODE 0: ignored
    const float* __restrict__ W,     // [1024, Ntot] row-major
    const float* __restrict__ bias, float* __restrict__ out)
{
    const int Ntot = (MODE == 1) ? 3072 : 1024;
    extern __shared__ char smem[];
    const uint32_t sb = smem_u32(smem);

    const int tid  = threadIdx.x;
    const int lane = tid & 31;
    const int wid  = tid >> 5;
    const int wm   = wid & 1;       // 2 warps along M (32 rows each)
    const int wn   = wid >> 1;      // 4 warps along N (32 cols each)

    const int col0 = blockIdx.x * 128;
    const int row0 = blockIdx.y * 64;

    const float* A = (MODE == 0) ? (const float*)g_attn : Ain;

    // Copy-phase: row = tid>>2 (0..63); A: 16 fp32 at col (tid&3)*16;
    // B: 2 x 16 fp32 at cols (tid&3)*16 and +64 (row stride 256B).
    const int cpR = tid >> 2;
    const int cpC = (tid & 3) * 16;
    const int cpU = (tid & 3) * 2;       // 16B unit within 128B half

    F4a c00 = {0,0,0,0}, c01 = {0,0,0,0}, c02 = {0,0,0,0}, c03 = {0,0,0,0};
    F4a c10 = {0,0,0,0}, c11 = {0,0,0,0}, c12 = {0,0,0,0}, c13 = {0,0,0,0};

    const int a_r  = wm * 32 + (lane & 15); // + mt*16 (same &7)
    const int a_s7 = a_r & 7;
    const int b_rl = lane & 15;             // + ks*16
    const int b_c0 = wn * 4 + (lane >> 4);  // first 16B n-chunk pair
    const int b_c1 = b_c0 + 2;              // second pair
    // chunk -> byte offset within a 256B row: half = c>>3, unit = c&7
    const int b_h0 = (b_c0 >> 3) << 7;
    const int b_u0 = b_c0 & 7;
    const int b_h1 = (b_c1 >> 3) << 7;
    const int b_u1 = b_c1 & 7;

#pragma unroll 1
    for (int kb = 0; kb < NKB; kb++) {
        const int kbase = kb * BK;

        __syncthreads();   // previous iteration's mma reads complete

        // ---- A phase: 16 fp32 -> swizzled hi/lo (128B rows) ----
        {
            const float* src = A + (size_t)(row0 + cpR) * GK + kbase + cpC;
            float4 f0 = *(const float4*)(src + 0);
            float4 f1 = *(const float4*)(src + 4);
            float4 f2 = *(const float4*)(src + 8);
            float4 f3 = *(const float4*)(src + 12);
            uint4 hi, lo;
            cvt8(f0, f1, hi, lo);
            uint32_t off = cpR * 128 + (((cpU + 0) ^ (cpR & 7)) << 4);
            *(uint4*)(smem + G_AH + off) = hi;
            *(uint4*)(smem + G_AL + off) = lo;
            cvt8(f2, f3, hi, lo);
            off = cpR * 128 + (((cpU + 1) ^ (cpR & 7)) << 4);
            *(uint4*)(smem + G_AH + off) = hi;
            *(uint4*)(smem + G_AL + off) = lo;
        }
        // ---- B phase: 2 x 16 fp32 -> swizzled hi/lo (256B rows, per-half) ----
        {
            const float* src = W + (size_t)(kbase + cpR) * Ntot + col0 + cpC;
            float4 f0 = *(const float4*)(src + 0);
            float4 f1 = *(const float4*)(src + 4);
            float4 f2 = *(const float4*)(src + 8);
            float4 f3 = *(const float4*)(src + 12);
            uint4 hi, lo;
            cvt8(f0, f1, hi, lo);
            uint32_t off = cpR * 256 + (((cpU + 0) ^ (cpR & 7)) << 4);
            *(uint4*)(smem + G_BH + off) = hi;
            *(uint4*)(smem + G_BL + off) = lo;
            cvt8(f2, f3, hi, lo);
            off = cpR * 256 + (((cpU + 1) ^ (cpR & 7)) << 4);
            *(uint4*)(smem + G_BH + off) = hi;
            *(uint4*)(smem + G_BL + off) = lo;
        }
        {
            const float* src = W + (size_t)(kbase + cpR) * Ntot + col0 + 64 + cpC;
            float4 f0 = *(const float4*)(src + 0);
            float4 f1 = *(const float4*)(src + 4);
            float4 f2 = *(const float4*)(src + 8);
            float4 f3 = *(const float4*)(src + 12);
            uint4 hi, lo;
            cvt8(f0, f1, hi, lo);
            uint32_t off = cpR * 256 + 128 + (((cpU + 0) ^ (cpR & 7)) << 4);
            *(uint4*)(smem + G_BH + off) = hi;
            *(uint4*)(smem + G_BL + off) = lo;
            cvt8(f2, f3, hi, lo);
            off = cpR * 256 + 128 + (((cpU + 1) ^ (cpR & 7)) << 4);
            *(uint4*)(smem + G_BH + off) = hi;
            *(uint4*)(smem + G_BL + off) = lo;
        }

        __syncthreads();

        // ---- mma: 4 k-steps of 16, warp tile 32x32 ----
#pragma unroll 1
        for (int ks = 0; ks < 4; ks++) {
            const int br = ks * 16 + b_rl;
            const uint32_t boff0 = br * 256 + b_h0 + ((b_u0 ^ (br & 7)) << 4);
            const uint32_t boff1 = br * 256 + b_h1 + ((b_u1 ^ (br & 7)) << 4);
            U4 bH0, bL0, bH1, bL1;
            ldsm4t(bH0, sb + G_BH + boff0);
            ldsm4t(bL0, sb + G_BL + boff0);
            ldsm4t(bH1, sb + G_BH + boff1);
            ldsm4t(bL1, sb + G_BL + boff1);

            const uint32_t asw = (uint32_t)(((2 * ks + (lane >> 4)) ^ a_s7) << 4);
            U4 aH, aL;
            // mt = 0
            ldsm4(aH, sb + G_AH + a_r * 128 + asw);
            ldsm4(aL, sb + G_AL + a_r * 128 + asw);
            MMA3(c00, bH0.x, bH0.y, bL0.x, bL0.y)
            MMA3(c01, bH0.z, bH0.w, bL0.z, bL0.w)
            MMA3(c02, bH1.x, bH1.y, bL1.x, bL1.y)
            MMA3(c03, bH1.z, bH1.w, bL1.z, bL1.w)
            // mt = 1
            ldsm4(aH, sb + G_AH + (a_r + 16) * 128 + asw);
            ldsm4(aL, sb + G_AL + (a_r + 16) * 128 + asw);
            MMA3(c10, bH0.x, bH0.y, bL0.x, bL0.y)
            MMA3(c11, bH0.z, bH0.w, bL0.z, bL0.w)
            MMA3(c12, bH1.x, bH1.y, bL1.x, bL1.y)
            MMA3(c13, bH1.z, bH1.w, bL1.z, bL1.w)
        }
    }

    EPI(c00, 0, 0); EPI(c01, 0, 1); EPI(c02, 0, 2); EPI(c03, 0, 3);
    EPI(c10, 1, 0); EPI(c11, 1, 1); EPI(c12, 1, 2); EPI(c13, 1, 3);
}

// ---------------------------------------------------------------------------
// RoPE on q and k in place (fp32) — verbatim.
// ---------------------------------------------------------------------------
struct RopeInv { float v[32]; };

__global__ __launch_bounds__(256) void rope_kernel(RopeInv tab) {
    const int idx = blockIdx.x * blockDim.x + threadIdx.x;
    const int d   = idx & 31;
    const int row = idx >> 5;
    const int t   = row & (T_ - 1);

    const float ang = (float)t * tab.v[d];
    float s, c;
    sincosf(ang, &s, &c);

    const size_t base = (size_t)row * DH_;
    {
        float x1 = g_q[base + d], x2 = g_q[base + d + 32];
        g_q[base + d]      = x1 * c - x2 * s;
        g_q[base + d + 32] = x1 * s + x2 * c;
    }
    {
        float x1 = g_k[base + d], x2 = g_k[base + d + 32];
        g_k[base + d]      = x1 * c - x2 * s;
        g_k[base + d + 32] = x1 * s + x2 * c;
    }
}

// ---------------------------------------------------------------------------
// Tensor-core flash attention — verbatim from passing R12.
// ---------------------------------------------------------------------------
#define A_QH 0
#define A_QL 8192
#define A_KH 16384
#define A_KL 24576
#define A_VH 32768
#define A_VL 40960
#define A_PH 49152
#define A_PL 57344
#define A_PS 65536
#define A_MS 82944
#define A_LS 83200
#define A_CS 83456
#define ATTN_SMEM 83712

__global__ __launch_bounds__(256) void attn_mma_kernel() {
    extern __shared__ char sm8[];
    const uint32_t sb = smem_u32(sm8);
    float* Ps = (float*)(sm8 + A_PS);     // [64][68]
    float* ms = (float*)(sm8 + A_MS);
    float* ls = (float*)(sm8 + A_LS);
    float* cs = (float*)(sm8 + A_CS);

    const int tid  = threadIdx.x;
    const int lane = tid & 31;
    const int wid  = tid >> 5;
    const int wm   = wid & 1;
    const int wn   = wid >> 1;

    const int bh = blockIdx.y;
    const int qb = blockIdx.x;

    const float* Qg = g_q + (size_t)bh * (T_ * DH_) + (size_t)qb * (64 * DH_);
    const float* Kg = g_k + (size_t)bh * (T_ * DH_);
    const float* Vg = g_v + (size_t)bh * (T_ * DH_);

    const int cpR = tid >> 2;
    const int cpC = (tid & 3) * 16;
    const int cpU = (tid & 3) * 2;

    {
        const float* src = Qg + (size_t)cpR * DH_ + cpC;
        float4 f0 = *(const float4*)(src + 0);
        float4 f1 = *(const float4*)(src + 4);
        float4 f2 = *(const float4*)(src + 8);
        float4 f3 = *(const float4*)(src + 12);
        f0.x *= 0.125f; f0.y *= 0.125f; f0.z *= 0.125f; f0.w *= 0.125f;
        f1.x *= 0.125f; f1.y *= 0.125f; f1.z *= 0.125f; f1.w *= 0.125f;
        f2.x *= 0.125f; f2.y *= 0.125f; f2.z *= 0.125f; f2.w *= 0.125f;
        f3.x *= 0.125f; f3.y *= 0.125f; f3.z *= 0.125f; f3.w *= 0.125f;
        uint4 hi, lo;
        cvt8(f0, f1, hi, lo);
        uint32_t off = cpR * 128 + (((cpU + 0) ^ (cpR & 7)) << 4);
        *(uint4*)(sm8 + A_QH + off) = hi;
        *(uint4*)(sm8 + A_QL + off) = lo;
        cvt8(f2, f3, hi, lo);
        off = cpR * 128 + (((cpU + 1) ^ (cpR & 7)) << 4);
        *(uint4*)(sm8 + A_QH + off) = hi;
        *(uint4*)(sm8 + A_QL + off) = lo;
    }
    if (tid < 64) { ms[tid] = -1e30f; ls[tid] = 0.0f; }

    F4a o00 = {0,0,0,0}, o01 = {0,0,0,0};
    F4a o10 = {0,0,0,0}, o11 = {0,0,0,0};

    const int a_r  = wm * 32 + (lane & 15);
    const int a_s7 = a_r & 7;
    const int k_r  = wn * 16 + ((lane >> 4) << 3) + (lane & 7);
    const int k_c  = (lane >> 3) & 1;
    const int v_rl = lane & 15;
    const int v_ch = wn * 2 + (lane >> 4);

#pragma unroll 1
    for (int kt = 0; kt < 32; kt++) {
        __syncthreads();

        {
            const float* src = Kg + (size_t)(kt * 64 + cpR) * DH_ + cpC;
            float4 f0 = *(const float4*)(src + 0);
            float4 f1 = *(const float4*)(src + 4);
            float4 f2 = *(const float4*)(src + 8);
            float4 f3 = *(const float4*)(src + 12);
            uint4 hi, lo;
            cvt8(f0, f1, hi, lo);
            uint32_t off = cpR * 128 + (((cpU + 0) ^ (cpR & 7)) << 4);
            *(uint4*)(sm8 + A_KH + off) = hi;
            *(uint4*)(sm8 + A_KL + off) = lo;
            cvt8(f2, f3, hi, lo);
            off = cpR * 128 + (((cpU + 1) ^ (cpR & 7)) << 4);
            *(uint4*)(sm8 + A_KH + off) = hi;
            *(uint4*)(sm8 + A_KL + off) = lo;
        }
        {
            const float* src = Vg + (size_t)(kt * 64 + cpR) * DH_ + cpC;
            float4 f0 = *(const float4*)(src + 0);
            float4 f1 = *(const float4*)(src + 4);
            float4 f2 = *(const float4*)(src + 8);
            float4 f3 = *(const float4*)(src + 12);
            uint4 hi, lo;
            cvt8(f0, f1, hi, lo);
            uint32_t off = cpR * 128 + (((cpU + 0) ^ (cpR & 7)) << 4);
            *(uint4*)(sm8 + A_VH + off) = hi;
            *(uint4*)(sm8 + A_VL + off) = lo;
            cvt8(f2, f3, hi, lo);
            off = cpR * 128 + (((cpU + 1) ^ (cpR & 7)) << 4);
            *(uint4*)(sm8 + A_VH + off) = hi;
            *(uint4*)(sm8 + A_VL + off) = lo;
        }
        __syncthreads();

        {
            F4a s00 = {0,0,0,0}, s01 = {0,0,0,0};
            F4a s10 = {0,0,0,0}, s11 = {0,0,0,0};
#pragma unroll 1
            for (int ks = 0; ks < 4; ks++) {
                const uint32_t koff = k_r * 128 + (((2 * ks + k_c) ^ (k_r & 7)) << 4);
                U4 bH, bL;
                ldsm4(bH, sb + A_KH + koff);
                ldsm4(bL, sb + A_KL + koff);
                const uint32_t asw = (uint32_t)(((2 * ks + (lane >> 4)) ^ a_s7) << 4);
                U4 aH, aL;
                ldsm4(aH, sb + A_QH + a_r * 128 + asw);
                ldsm4(aL, sb + A_QL + a_r * 128 + asw);
                MMA3(s00, bH.x, bH.y, bL.x, bL.y)
                MMA3(s01, bH.z, bH.w, bL.z, bL.w)
                ldsm4(aH, sb + A_QH + (a_r + 16) * 128 + asw);
                ldsm4(aL, sb + A_QL + (a_r + 16) * 128 + asw);
                MMA3(s10, bH.x, bH.y, bL.x, bL.y)
                MMA3(s11, bH.z, bH.w, bL.z, bL.w)
            }
            const int r0 = wm * 32 + (lane >> 2);
            const int cB = wn * 16 + 2 * (lane & 3);
            *(float2*)(Ps + (r0 +  0) * 68 + cB)     = make_float2(s00.x, s00.y);
            *(float2*)(Ps + (r0 +  8) * 68 + cB)     = make_float2(s00.z, s00.w);
            *(float2*)(Ps + (r0 +  0) * 68 + cB + 8) = make_float2(s01.x, s01.y);
            *(float2*)(Ps + (r0 +  8) * 68 + cB + 8) = make_float2(s01.z, s01.w);
            *(float2*)(Ps + (r0 + 16) * 68 + cB)     = make_float2(s10.x, s10.y);
            *(float2*)(Ps + (r0 + 24) * 68 + cB)     = make_float2(s10.z, s10.w);
            *(float2*)(Ps + (r0 + 16) * 68 + cB + 8) = make_float2(s11.x, s11.y);
            *(float2*)(Ps + (r0 + 24) * 68 + cB + 8) = make_float2(s11.z, s11.w);
        }
        __syncthreads();

        {
            const int row = tid >> 2;
            const int q   = tid & 3;
            const float* pr = Ps + row * 68 + q * 16;
            float4 p0 = *(const float4*)(pr + 0);
            float4 p1 = *(const float4*)(pr + 4);
            float4 p2 = *(const float4*)(pr + 8);
            float4 p3 = *(const float4*)(pr + 12);
            float mx = fmaxf(fmaxf(fmaxf(p0.x, p0.y), fmaxf(p0.z, p0.w)),
                             fmaxf(fmaxf(p1.x, p1.y), fmaxf(p1.z, p1.w)));
            mx = fmaxf(mx, fmaxf(fmaxf(fmaxf(p2.x, p2.y), fmaxf(p2.z, p2.w)),
                                 fmaxf(fmaxf(p3.x, p3.y), fmaxf(p3.z, p3.w))));
            mx = fmaxf(mx, __shfl_xor_sync(0xffffffffu, mx, 1));
            mx = fmaxf(mx, __shfl_xor_sync(0xffffffffu, mx, 2));
            const float m_old = ms[row];
            const float m_new = fmaxf(m_old, mx);
            p0.x = __expf(p0.x - m_new); p0.y = __expf(p0.y - m_new);
            p0.z = __expf(p0.z - m_new); p0.w = __expf(p0.w - m_new);
            p1.x = __expf(p1.x - m_new); p1.y = __expf(p1.y - m_new);
            p1.z = __expf(p1.z - m_new); p1.w = __expf(p1.w - m_new);
            p2.x = __expf(p2.x - m_new); p2.y = __expf(p2.y - m_new);
            p2.z = __expf(p2.z - m_new); p2.w = __expf(p2.w - m_new);
            p3.x = __expf(p3.x - m_new); p3.y = __expf(p3.y - m_new);
            p3.z = __expf(p3.z - m_new); p3.w = __expf(p3.w - m_new);
            float sum = p0.x + p0.y + p0.z + p0.w + p1.x + p1.y + p1.z + p1.w
                      + p2.x + p2.y + p2.z + p2.w + p3.x + p3.y + p3.z + p3.w;
            sum += __shfl_xor_sync(0xffffffffu, sum, 1);
            sum += __shfl_xor_sync(0xffffffffu, sum, 2);
            const float corr = __expf(m_old - m_new);
            if (q == 0) {
                ms[row] = m_new;
                cs[row] = corr;
                ls[row] = ls[row] * corr + sum;
            }
            uint4 hi, lo;
            cvt8(p0, p1, hi, lo);
            uint32_t off = row * 128 + (((cpU + 0) ^ (row & 7)) << 4);
            *(uint4*)(sm8 + A_PH + off) = hi;
            *(uint4*)(sm8 + A_PL + off) = lo;
            cvt8(p2, p3, hi, lo);
            off = row * 128 + (((cpU + 1) ^ (row & 7)) << 4);
            *(uint4*)(sm8 + A_PH + off) = hi;
            *(uint4*)(sm8 + A_PL + off) = lo;
        }
        __syncthreads();

        {
            const int r0 = wm * 32 + (lane >> 2);
            const float c0l = cs[r0],      c0h = cs[r0 + 8];
            const float c1l = cs[r0 + 16], c1h = cs[r0 + 24];
            o00.x *= c0l; o00.y *= c0l; o00.z *= c0h; o00.w *= c0h;
            o01.x *= c0l; o01.y *= c0l; o01.z *= c0h; o01.w *= c0h;
            o10.x *= c1l; o10.y *= c1l; o10.z *= c1h; o10.w *= c1h;
            o11.x *= c1l; o11.y *= c1l; o11.z *= c1h; o11.w *= c1h;
#pragma unroll 1
            for (int ks = 0; ks < 4; ks++) {
                const int vr = ks * 16 + v_rl;
                const uint32_t voff = vr * 128 + ((v_ch ^ (vr & 7)) << 4);
                U4 bH, bL;
                ldsm4t(bH, sb + A_VH + voff);
                ldsm4t(bL, sb + A_VL + voff);
                const uint32_t asw = (uint32_t)(((2 * ks + (lane >> 4)) ^ a_s7) << 4);
                U4 aH, aL;
                ldsm4(aH, sb + A_PH + a_r * 128 + asw);
                ldsm4(aL, sb + A_PL + a_r * 128 + asw);
                MMA3(o00, bH.x, bH.y, bL.x, bL.y)
                MMA3(o01, bH.z, bH.w, bL.z, bL.w)
                ldsm4(aH, sb + A_PH + (a_r + 16) * 128 + asw);
                ldsm4(aL, sb + A_PL + (a_r + 16) * 128 + asw);
                MMA3(o10, bH.x, bH.y, bL.x, bL.y)
                MMA3(o11, bH.z, bH.w, bL.z, bL.w)
            }
        }
    }

    {
        const int r0  = wm * 32 + (lane >> 2);
        const int dcB = wn * 16 + 2 * (lane & 3);
        const float i0l = 1.0f / ls[r0],      i0h = 1.0f / ls[r0 + 8];
        const float i1l = 1.0f / ls[r0 + 16], i1h = 1.0f / ls[r0 + 24];
        const int bb = bh >> 4;
        const int h  = bh & 15;
        float* obase = g_attn + ((size_t)(bb * T_ + qb * 64)) * D_ + h * DH_;
        *(float2*)(obase + (size_t)(r0 +  0) * D_ + dcB)     = make_float2(o00.x * i0l, o00.y * i0l);
        *(float2*)(obase + (size_t)(r0 +  8) * D_ + dcB)     = make_float2(o00.z * i0h, o00.w * i0h);
        *(float2*)(obase + (size_t)(r0 +  0) * D_ + dcB + 8) = make_float2(o01.x * i0l, o01.y * i0l);
        *(float2*)(obase + (size_t)(r0 +  8) * D_ + dcB + 8) = make_float2(o01.z * i0h, o01.w * i0h);
        *(float2*)(obase + (size_t)(r0 + 16) * D_ + dcB)     = make_float2(o10.x * i1l, o10.y * i1l);
        *(float2*)(obase + (size_t)(r0 + 24) * D_ + dcB)     = make_float2(o10.z * i1h, o10.w * i1h);
        *(float2*)(obase + (size_t)(r0 + 16) * D_ + dcB + 8) = make_float2(o11.x * i1l, o11.y * i1l);
        *(float2*)(obase + (size_t)(r0 + 24) * D_ + dcB + 8) = make_float2(o11.z * i1h, o11.w * i1h);
    }
}

// ---------------------------------------------------------------------------
extern "C" void kernel_launch(void* const* d_in, const int* in_sizes, int n_in,
                              void* d_out, int out_size)
{
    const float* x     = (const float*)d_in[0];
    const float* Wqkv  = (const float*)d_in[1];
    const float* bqkv  = (const float*)d_in[2];
    const float* Wproj = (const float*)d_in[3];
    const float* bproj = (const float*)d_in[4];
    float* out = (float*)d_out;

    cudaFuncSetAttribute((const void*)gemm_fused_kernel<1>,
                         cudaFuncAttributeMaxDynamicSharedMemorySize, GEMM_SMEM);
    cudaFuncSetAttribute((const void*)gemm_fused_kernel<0>,
                         cudaFuncAttributeMaxDynamicSharedMemorySize, GEMM_SMEM);
    cudaFuncSetAttribute((const void*)attn_mma_kernel,
                         cudaFuncAttributeMaxDynamicSharedMemorySize, ATTN_SMEM);

    // 1) QKV GEMM (wide 64x128 tiles) + head scatter
    gemm_fused_kernel<1><<<dim3(24, 128), 256, GEMM_SMEM>>>(x, Wqkv, bqkv, nullptr);

    // 2) RoPE
    RopeInv tab;
    for (int d = 0; d < 32; d++)
        tab.v[d] = (float)(1.0 / pow(10000.0, (double)((float)d / 32.0f)));
    rope_kernel<<<16384, 256>>>(tab);

    // 3) Flash attention (mma.sync, proven R12)
    attn_mma_kernel<<<dim3(32, 64), 256, ATTN_SMEM>>>();

    // 4) Output projection (wide tiles)
    gemm_fused_kernel<0><<<dim3(8, 128), 256, GEMM_SMEM>>>(nullptr, Wproj, bproj, out);
}